// round 13
// baseline (speedup 1.0000x reference)
#include <cuda_runtime.h>

#define FP      80
#define MTAPS   24
#define NSTAGES 20
#define BATCH   8
#define NFRAMES 1024
#define TLEN    (NFRAMES * FP)        // 81920

#define RPT     8                     // 8 | 80 -> thread never crosses a frame
#define BLOCK   352                   // 11 warps; 2 blocks/SM (reg cap 93)
#define WINW    (BLOCK * RPT)         // 2816
#define HALO    (NSTAGES * MTAPS)     // 480
#define TBOUT   (WINW - HALO)         // 2336 (mult of 8 -> alignment holds)
#define PADZ    24
#define BPB     ((TLEN + TBOUT - 1) / TBOUT)   // 36 -> grid 288 = 2/SM, one wave
#define NFR     (WINW / FP + 2)       // 37 frame rows per block window

typedef unsigned long long u64p;

__device__ __forceinline__ u64p pk2(float lo, float hi) {
    u64p r; asm("mov.b64 %0, {%1, %2};" : "=l"(r) : "f"(lo), "f"(hi)); return r;
}
__device__ __forceinline__ void upk2(u64p v, float& lo, float& hi) {
    asm("mov.b64 {%0, %1}, %2;" : "=f"(lo), "=f"(hi) : "l"(v));
}
__device__ __forceinline__ u64p ffma2(u64p a, u64p b, u64p c) {
    u64p d; asm("fma.rn.f32x2 %0, %1, %2, %3;" : "=l"(d) : "l"(a), "l"(b), "l"(c)); return d;
}
__device__ __forceinline__ u64p dup2(float v) { return pk2(v, v); }

__global__ void __launch_bounds__(BLOCK, 2)
fir_taylor_kernel(const float* __restrict__ x,
                  const float* __restrict__ mc,
                  const float* __restrict__ a,
                  const float* __restrict__ wts,
                  float* __restrict__ out)
{
    __shared__ float buf0[WINW + PADZ];
    __shared__ float buf1[WINW + PADZ];
    __shared__ u64p  s_kj[NFR * MTAPS];      // per-frame (c0_j, d_j/80)
    __shared__ float s_f[NSTAGES + 1];       // a[i] * prod_{k<=i} wts[k]

    const int tid = threadIdx.x;
    const int blk = blockIdx.x;
    const int b   = blk / BPB;
    const int tb  = blk % BPB;
    const int t0  = tb * TBOUT;
    const int g0  = t0 - HALO;
    const int n_min = (g0 > 0 ? g0 : 0) / FP;

    if (tid == 0) {
        float P = 1.0f;
        s_f[0] = a[0];
        for (int i = 1; i <= NSTAGES; i++) { P *= wts[i]; s_f[i] = a[i] * P; }
    }
    if (tid < PADZ) { buf0[tid] = 0.0f; buf1[tid] = 0.0f; }

    // fill shared coefficient table (per-frame, shared by ~10 threads/row)
    {
        const float invP = 1.0f / (float)FP;
        for (int e = tid; e < NFR * MTAPS; e += BLOCK) {
            int row = e / MTAPS, j = e % MTAPS;
            int n  = n_min + row; if (n > NFRAMES - 1) n = NFRAMES - 1;
            int n1 = n + 1;       if (n1 > NFRAMES - 1) n1 = NFRAMES - 1;
            float c0 = mc[((long)b * NFRAMES + n)  * (MTAPS + 1) + j + 1];
            float c1 = mc[((long)b * NFRAMES + n1) * (MTAPS + 1) + j + 1];
            s_kj[e] = pk2(c0, (c1 - c0) * invP);
        }
    }

    const int lp    = tid * RPT;
    const int tbase = g0 + lp;

    // own 8 samples -> regs + smem (state 0)
    const float* xb = x + b * TLEN;
    float acc[RPT];
#pragma unroll
    for (int r = 0; r < RPT; r++) {
        int t = tbase + r;
        acc[r] = (t >= 0 && t < TLEN) ? __ldg(xb + t) : 0.0f;
    }
    {
        float4* st = (float4*)(buf0 + PADZ + lp);
        float4 f0; f0.x = acc[0]; f0.y = acc[1]; f0.z = acc[2]; f0.w = acc[3];
        float4 f1; f1.x = acc[4]; f1.y = acc[5]; f1.z = acc[6]; f1.w = acc[7];
        st[0] = f0; st[1] = f1;
    }

    // per-thread frame row + phase
    int tc = tbase < 0 ? 0 : (tbase >= TLEN ? TLEN - 1 : tbase);
    int n  = tc / FP;
    const float pf = (float)(tc - n * FP);        // integer phase 0..72
    const volatile u64p* krow = s_kj + (n - n_min) * MTAPS;

    // K epilogue params
    const float invP = 1.0f / (float)FP;
    int n1 = (n + 1 < NFRAMES) ? n + 1 : NFRAMES - 1;
    const float k0 = mc[((long)b * NFRAMES + n)  * (MTAPS + 1)];
    const float dk = mc[((long)b * NFRAMES + n1) * (MTAPS + 1)] - k0;

    __syncthreads();

    // packed y accumulators
    u64p y01, y23, y45, y67;
    {
        u64p a0 = dup2(s_f[0]);
        y01 = ffma2(pk2(acc[0], acc[1]), a0, 0ULL);
        y23 = ffma2(pk2(acc[2], acc[3]), a0, 0ULL);
        y45 = ffma2(pk2(acc[4], acc[5]), a0, 0ULL);
        y67 = ffma2(pk2(acc[6], acc[7]), a0, 0ULL);
    }

    float* cur = buf0;
    float* nxt = buf1;

#pragma unroll 1
    for (int i = 1; i <= NSTAGES; i++) {
        // halo w[0..23] = cur[lp-24 .. lp-1]
        float w[MTAPS];
        {
            const float4* v = (const float4*)(cur + PADZ + lp - MTAPS);
#pragma unroll
            for (int q = 0; q < MTAPS / 4; q++) {
                float4 f = v[q];
                w[4*q+0] = f.x; w[4*q+1] = f.y; w[4*q+2] = f.z; w[4*q+3] = f.w;
            }
        }

        // 8-chain MAC, one kj load per tap (volatile -> stays in smem)
        u64p ab[RPT];
#pragma unroll
        for (int r = 0; r < RPT; r++) ab[r] = 0ULL;
#pragma unroll
        for (int j = 1; j <= MTAPS; j++) {
            u64p k = krow[j - 1];
#pragma unroll
            for (int r = 0; r < RPT; r++) {
                int idx = MTAPS + r - j;
                float v = (idx >= MTAPS) ? acc[idx - MTAPS] : w[idx];
                ab[r] = ffma2(dup2(v), k, ab[r]);
            }
        }

        float na[RPT];
#pragma unroll
        for (int r = 0; r < RPT; r++) {
            float A, B;
            upk2(ab[r], A, B);
            na[r] = fmaf(pf + (float)r, B, A);       // s(r) = A + (pf+r)*B
        }

        // publish next state, update y (packed), rotate
        if (i < NSTAGES) {
            float4* st = (float4*)(nxt + PADZ + lp);
            float4 f0; f0.x = na[0]; f0.y = na[1]; f0.z = na[2]; f0.w = na[3];
            float4 f1; f1.x = na[4]; f1.y = na[5]; f1.z = na[6]; f1.w = na[7];
            st[0] = f0; st[1] = f1;
        }

        {
            u64p fi2 = dup2(s_f[i]);
            y01 = ffma2(pk2(na[0], na[1]), fi2, y01);
            y23 = ffma2(pk2(na[2], na[3]), fi2, y23);
            y45 = ffma2(pk2(na[4], na[5]), fi2, y45);
            y67 = ffma2(pk2(na[6], na[7]), fi2, y67);
        }
#pragma unroll
        for (int r = 0; r < RPT; r++) acc[r] = na[r];

        if (i < NSTAGES) {
            __syncthreads();
            float* tmp = cur; cur = nxt; nxt = tmp;
        }
    }

    // ---- epilogue: out = y * exp(interp(mc[...,0])) ----
    if (lp >= HALO) {
        float yv[RPT];
        upk2(y01, yv[0], yv[1]);
        upk2(y23, yv[2], yv[3]);
        upk2(y45, yv[4], yv[5]);
        upk2(y67, yv[6], yv[7]);
        float* ob = out + b * TLEN;
#pragma unroll
        for (int r = 0; r < RPT; r++) {
            int tt = tbase + r;
            if (tt < TLEN) {
                float K = expf(fmaf(fmaf(pf + (float)r, invP, 0.0f), dk, k0));
                ob[tt] = yv[r] * K;
            }
        }
    }
}

extern "C" void kernel_launch(void* const* d_in, const int* in_sizes, int n_in,
                              void* d_out, int out_size)
{
    (void)in_sizes; (void)n_in; (void)out_size;
    const float* x   = (const float*)d_in[0];
    const float* mc  = (const float*)d_in[1];
    const float* a   = (const float*)d_in[2];
    const float* wts = (const float*)d_in[3];
    float* out = (float*)d_out;

    fir_taylor_kernel<<<BATCH * BPB, BLOCK>>>(x, mc, a, wts, out);
}